// round 9
// baseline (speedup 1.0000x reference)
#include <cuda_runtime.h>

// Scaled dot-product attention, B=4 H=16 S=2048 D=64, fp32 in/out.
// Flash-attention on tensor cores: mma.sync.m16n8k8 tf32.
// CTA: 128 q x 128 k per iteration, 8 warps in a 4(M) x 2(N) grid.
// Warp = 32 q-rows x 64 k-cols; PV is split-K across the 2 N-warps,
// partial O summed in the epilogue. B-fragments reused across 2 m-tiles.

#define DH 64
#define BM 128
#define BN 128
#define NT 256

#define KS_STRIDE 68   /* words per K row (conflict-free for gid*?+tig pattern) */
#define VS_STRIDE 72   /* words per V row */
#define KS_BYTES (BN * KS_STRIDE * 4)            /* 34816 */
#define VS_BYTES (BN * VS_STRIDE * 4)            /* 36864 */
#define RED_OFF  (KS_BYTES + VS_BYTES)           /* 71680 */
#define RED_BYTES (8 * 2 * 16 * 2 * 4)           /* 2048: [warp][mt][row16][max,sum] */
#define SMEM_BYTES (RED_OFF + RED_BYTES)         /* 73728 */

__device__ __forceinline__ unsigned tf32b(float x) {
    unsigned u;
    asm("cvt.rna.tf32.f32 %0, %1;" : "=r"(u) : "f"(x));
    return u;
}
__device__ __forceinline__ float ex2f(float x) {
    float r; asm("ex2.approx.f32 %0, %1;" : "=f"(r) : "f"(x)); return r;
}
__device__ __forceinline__ void mma_tf32(float c[4],
                                         const unsigned a[4],
                                         unsigned b0, unsigned b1) {
    asm("mma.sync.aligned.m16n8k8.row.col.f32.tf32.tf32.f32 "
        "{%0,%1,%2,%3}, {%4,%5,%6,%7}, {%8,%9}, {%0,%1,%2,%3};"
        : "+f"(c[0]), "+f"(c[1]), "+f"(c[2]), "+f"(c[3])
        : "r"(a[0]), "r"(a[1]), "r"(a[2]), "r"(a[3]), "r"(b0), "r"(b1));
}

__global__ void __launch_bounds__(NT, 1) attn_tf32_split_kernel(
    const float* __restrict__ Q,
    const float* __restrict__ K,
    const float* __restrict__ V,
    float* __restrict__ O,
    int S)
{
    extern __shared__ char smem[];
    unsigned* Ks = (unsigned*)smem;               // tf32 bits, K[row][d]
    unsigned* Vs = (unsigned*)(smem + KS_BYTES);  // tf32 bits, V[row][d]
    float* red = (float*)(smem + RED_OFF);        // [warp][mt][row16][2]

    const int tid  = threadIdx.x;
    const int lane = tid & 31;
    const int warp = tid >> 5;
    const int mi   = warp >> 1;   // 0..3: 32-row group
    const int ni   = warp & 1;    // 0..1: 64-col / key-half group
    const int gid  = lane >> 2;
    const int tig  = lane & 3;

    const size_t base = (size_t)blockIdx.y * ((size_t)S * DH);
    const int qbase = blockIdx.x * BM;

    // ---- stage Q (scaled to log2 domain, tf32) into Ks ----
    const float SC = 0.125f * 1.4426950408889634f;
    #pragma unroll
    for (int it = 0; it < 8; ++it) {
        int idx = tid + it * NT;
        int row = idx >> 4;
        int d4 = (idx & 15) << 2;
        float4 v = *(const float4*)&Q[base + (size_t)(qbase + row) * DH + d4];
        uint4 u;
        u.x = tf32b(v.x * SC); u.y = tf32b(v.y * SC);
        u.z = tf32b(v.z * SC); u.w = tf32b(v.w * SC);
        *(uint4*)&Ks[row * KS_STRIDE + d4] = u;
    }
    __syncthreads();

    // ---- Q fragments resident: 8 d-chunks x 2 m-tiles ----
    unsigned qa[8][2][4];
    #pragma unroll
    for (int kc = 0; kc < 8; ++kc) {
        #pragma unroll
        for (int mt = 0; mt < 2; ++mt) {
            const int r = mi * 32 + mt * 16 + gid;
            qa[kc][mt][0] = Ks[(r    ) * KS_STRIDE + kc * 8 + tig];
            qa[kc][mt][1] = Ks[(r + 8) * KS_STRIDE + kc * 8 + tig];
            qa[kc][mt][2] = Ks[(r    ) * KS_STRIDE + kc * 8 + tig + 4];
            qa[kc][mt][3] = Ks[(r + 8) * KS_STRIDE + kc * 8 + tig + 4];
        }
    }

    float o[2][8][4];     // partial O: 2 m-tiles x 8 dh-tiles (keys: this warp's half)
    #pragma unroll
    for (int mt = 0; mt < 2; ++mt)
        #pragma unroll
        for (int nt = 0; nt < 8; ++nt)
            #pragma unroll
            for (int j = 0; j < 4; ++j) o[mt][nt][j] = 0.0f;
    float m[2][2], l[2][2];
    #pragma unroll
    for (int mt = 0; mt < 2; ++mt) {
        m[mt][0] = m[mt][1] = -1e30f;
        l[mt][0] = l[mt][1] = 0.0f;
    }

    const int srcA = (lane & 28) | (tig >> 1);
    const int srcB = srcA + 2;
    const bool oddl = (tig & 1) != 0;

    const int nkt = S / BN;
    for (int kt = 0; kt < nkt; ++kt) {
        const int kb = kt * BN;
        __syncthreads();   // Q-frag / prev-iter smem reads complete

        // ---- stage K and V tiles (tf32 bits) ----
        #pragma unroll
        for (int it = 0; it < 8; ++it) {
            int idx = tid + it * NT;
            int row = idx >> 4;
            int d4 = (idx & 15) << 2;
            float4 v = *(const float4*)&K[base + (size_t)(kb + row) * DH + d4];
            uint4 u;
            u.x = tf32b(v.x); u.y = tf32b(v.y); u.z = tf32b(v.z); u.w = tf32b(v.w);
            *(uint4*)&Ks[row * KS_STRIDE + d4] = u;
        }
        #pragma unroll
        for (int it = 0; it < 8; ++it) {
            int idx = tid + it * NT;
            int row = idx >> 4;
            int d4 = (idx & 15) << 2;
            float4 v = *(const float4*)&V[base + (size_t)(kb + row) * DH + d4];
            uint4 u;
            u.x = tf32b(v.x); u.y = tf32b(v.y); u.z = tf32b(v.z); u.w = tf32b(v.w);
            *(uint4*)&Vs[row * VS_STRIDE + d4] = u;
        }
        __syncthreads();

        // ---- GEMM1: S = Q @ K^T; warp covers 32 rows x cols [ni*64, ni*64+64) ----
        float c[2][8][4];
        #pragma unroll
        for (int mt = 0; mt < 2; ++mt)
            #pragma unroll
            for (int nt = 0; nt < 8; ++nt)
                #pragma unroll
                for (int j = 0; j < 4; ++j) c[mt][nt][j] = 0.0f;

        #pragma unroll
        for (int kc = 0; kc < 8; ++kc) {
            #pragma unroll
            for (int nt = 0; nt < 8; ++nt) {
                const int krow = ni * 64 + nt * 8 + gid;
                unsigned b0 = Ks[krow * KS_STRIDE + kc * 8 + tig];
                unsigned b1 = Ks[krow * KS_STRIDE + kc * 8 + tig + 4];
                mma_tf32(c[0][nt], qa[kc][0], b0, b1);   // B reused across m-tiles
                mma_tf32(c[1][nt], qa[kc][1], b0, b1);
            }
        }

        // ---- partial softmax (own 64 cols), exchange with partner warp ----
        float pm[2][2], psum[2][2];
        #pragma unroll
        for (int mt = 0; mt < 2; ++mt) {
            float mx0 = -1e30f, mx1 = -1e30f;
            #pragma unroll
            for (int nt = 0; nt < 8; ++nt) {
                mx0 = fmaxf(mx0, fmaxf(c[mt][nt][0], c[mt][nt][1]));
                mx1 = fmaxf(mx1, fmaxf(c[mt][nt][2], c[mt][nt][3]));
            }
            #pragma unroll
            for (int off = 1; off <= 2; off <<= 1) {
                mx0 = fmaxf(mx0, __shfl_xor_sync(0xffffffffu, mx0, off));
                mx1 = fmaxf(mx1, __shfl_xor_sync(0xffffffffu, mx1, off));
            }
            float s0 = 0.0f, s1 = 0.0f;
            #pragma unroll
            for (int nt = 0; nt < 8; ++nt) {
                c[mt][nt][0] = ex2f(c[mt][nt][0] - mx0);
                c[mt][nt][1] = ex2f(c[mt][nt][1] - mx0);
                c[mt][nt][2] = ex2f(c[mt][nt][2] - mx1);
                c[mt][nt][3] = ex2f(c[mt][nt][3] - mx1);
                s0 += c[mt][nt][0] + c[mt][nt][1];
                s1 += c[mt][nt][2] + c[mt][nt][3];
            }
            #pragma unroll
            for (int off = 1; off <= 2; off <<= 1) {
                s0 += __shfl_xor_sync(0xffffffffu, s0, off);
                s1 += __shfl_xor_sync(0xffffffffu, s1, off);
            }
            pm[mt][0] = mx0; pm[mt][1] = mx1;
            psum[mt][0] = s0; psum[mt][1] = s1;
            if (tig == 0) {
                float* rb = red + ((warp * 2 + mt) * 16) * 2;
                rb[(gid    ) * 2 + 0] = mx0;  rb[(gid    ) * 2 + 1] = s0;
                rb[(gid + 8) * 2 + 0] = mx1;  rb[(gid + 8) * 2 + 1] = s1;
            }
        }
        __syncthreads();

        float ps[2][2];   // P rescale factors (power of 2, exact)
        #pragma unroll
        for (int mt = 0; mt < 2; ++mt) {
            const float* rb = red + (((warp ^ 1) * 2 + mt) * 16) * 2;
            #pragma unroll
            for (int h = 0; h < 2; ++h) {
                float qm = rb[(gid + 8 * h) * 2 + 0];
                float qs = rb[(gid + 8 * h) * 2 + 1];
                float M = fmaxf(m[mt][h], fmaxf(pm[mt][h], qm));
                float f = ex2f(m[mt][h] - M);
                float po = ex2f(pm[mt][h] - M);
                float pp = ex2f(qm - M);
                l[mt][h] = l[mt][h] * f + psum[mt][h] * po + qs * pp;
                m[mt][h] = M;
                ps[mt][h] = po;
                #pragma unroll
                for (int nt = 0; nt < 8; ++nt) {
                    o[mt][nt][2 * h + 0] *= f;
                    o[mt][nt][2 * h + 1] *= f;
                }
            }
        }

        // ---- GEMM2: O += P @ V over this warp's 64 keys ----
        #pragma unroll
        for (int kc = 0; kc < 8; ++kc) {
            unsigned pa[2][4];
            #pragma unroll
            for (int mt = 0; mt < 2; ++mt) {
                float x0 = __shfl_sync(0xffffffffu, c[mt][kc][0], srcA);
                float x1 = __shfl_sync(0xffffffffu, c[mt][kc][1], srcA);
                float y0 = __shfl_sync(0xffffffffu, c[mt][kc][0], srcB);
                float y1 = __shfl_sync(0xffffffffu, c[mt][kc][1], srcB);
                float z0 = __shfl_sync(0xffffffffu, c[mt][kc][2], srcA);
                float z1 = __shfl_sync(0xffffffffu, c[mt][kc][3], srcA);
                float w0 = __shfl_sync(0xffffffffu, c[mt][kc][2], srcB);
                float w1 = __shfl_sync(0xffffffffu, c[mt][kc][3], srcB);
                pa[mt][0] = tf32b((oddl ? x1 : x0) * ps[mt][0]);
                pa[mt][2] = tf32b((oddl ? y1 : y0) * ps[mt][0]);
                pa[mt][1] = tf32b((oddl ? z1 : z0) * ps[mt][1]);
                pa[mt][3] = tf32b((oddl ? w1 : w0) * ps[mt][1]);
            }
            #pragma unroll
            for (int nt2 = 0; nt2 < 8; ++nt2) {
                const int vr = ni * 64 + kc * 8 + tig;
                unsigned b0 = Vs[(vr    ) * VS_STRIDE + nt2 * 8 + gid];
                unsigned b1 = Vs[(vr + 4) * VS_STRIDE + nt2 * 8 + gid];
                mma_tf32(o[0][nt2], pa[0], b0, b1);     // B reused across m-tiles
                mma_tf32(o[1][nt2], pa[1], b0, b1);
            }
        }
    }

    // ---- epilogue: sum the two key-half partials, normalize, store ----
    __syncthreads();
    float* Obuf = (float*)smem;            // [128 rows][66], aliases Ks
    if (ni == 1) {
        #pragma unroll
        for (int mt = 0; mt < 2; ++mt) {
            const int r = mi * 32 + mt * 16 + gid;
            #pragma unroll
            for (int nt = 0; nt < 8; ++nt) {
                float2 v0 = { o[mt][nt][0], o[mt][nt][1] };
                float2 v1 = { o[mt][nt][2], o[mt][nt][3] };
                *(float2*)&Obuf[(r    ) * 66 + nt * 8 + 2 * tig] = v0;
                *(float2*)&Obuf[(r + 8) * 66 + nt * 8 + 2 * tig] = v1;
            }
        }
    }
    __syncthreads();
    if (ni == 0) {
        #pragma unroll
        for (int mt = 0; mt < 2; ++mt) {
            const float inv0 = 1.0f / l[mt][0];
            const float inv1 = 1.0f / l[mt][1];
            const int r = mi * 32 + mt * 16 + gid;
            #pragma unroll
            for (int nt = 0; nt < 8; ++nt) {
                float2 p0 = *(const float2*)&Obuf[(r    ) * 66 + nt * 8 + 2 * tig];
                float2 p1 = *(const float2*)&Obuf[(r + 8) * 66 + nt * 8 + 2 * tig];
                float2 e0, e1;
                e0.x = (o[mt][nt][0] + p0.x) * inv0;
                e0.y = (o[mt][nt][1] + p0.y) * inv0;
                e1.x = (o[mt][nt][2] + p1.x) * inv1;
                e1.y = (o[mt][nt][3] + p1.y) * inv1;
                *(float2*)&O[base + (size_t)(qbase + r    ) * DH + nt * 8 + 2 * tig] = e0;
                *(float2*)&O[base + (size_t)(qbase + r + 8) * DH + nt * 8 + 2 * tig] = e1;
            }
        }
    }
}

extern "C" void kernel_launch(void* const* d_in, const int* in_sizes, int n_in,
                              void* d_out, int out_size)
{
    const float* Q = (const float*)d_in[0];
    const float* K = (const float*)d_in[1];
    const float* V = (const float*)d_in[2];
    float* O = (float*)d_out;

    const int S = 2048;   // B=4, H=16, S=2048, D=64 fixed by the problem

    cudaFuncSetAttribute(attn_tf32_split_kernel,
                         cudaFuncAttributeMaxDynamicSharedMemorySize, SMEM_BYTES);

    dim3 grid(S / BM, 64);
    attn_tf32_split_kernel<<<grid, NT, SMEM_BYTES>>>(Q, K, V, O, S);
}